// round 3
// baseline (speedup 1.0000x reference)
#include <cuda_runtime.h>
#include <cstdint>
#include <cstddef>

// Problem shapes (fixed by the dataset):
//   inputs : [OUT=1024, D=8192] f32   (d_in[0])
//   adj    : [N=8192, IN=1024] f32    (d_in[1])
//   prob_AU: [N=8192] f32             (d_in[2])
//   w      : [IN=1024, OUT=1024] f32  (d_in[3])
// out buffer: [N*D] activation-output followed by [N*D] mask (0/1 float).

#define BMT 128
#define BNT 128
#define BKT 16
#define TM 8
#define TN 8

static const int N_ROWS = 8192;   // N
static const int K_IN   = 1024;   // IN
static const int K_OUT  = 1024;   // OUT
static const int D_COLS = 8192;   // D

// Scratch for T = adj @ (w/17): 8192 x 1024 f32 = 32 MB
__device__ float g_T[(size_t)8192 * 1024];

// EPI == 0 : C = A @ (B*bscale)          (GEMM1, writes g_T)
// EPI == 1 : pre = g_T @ B, fused epilogue -> C (out) and Mk (mask)
template <int EPI>
__global__ __launch_bounds__(256, 2)
void sgemm_k(const float* __restrict__ A, const float* __restrict__ B,
             float* __restrict__ C, float* __restrict__ Mk,
             const float* __restrict__ prob,
             int M, int N, int K, float bscale)
{
    __shared__ float As[BKT][BMT + 4];   // +4 keeps 16B alignment, trims STS conflicts
    __shared__ float Bs[BKT][BNT];

    const int tid = threadIdx.x;
    const int tx  = tid & 15;            // 0..15 -> col group
    const int ty  = tid >> 4;            // 0..15 -> row group
    const int bm  = blockIdx.y * BMT;
    const int bn  = blockIdx.x * BNT;

    const float* Ap = (EPI == 1) ? (const float*)g_T : A;
    float*       Cp = (EPI == 1) ? C : (float*)g_T;

    const float* Ab = Ap + (size_t)bm * K;
    const float* Bb = B + bn;

    float acc[TM][TN];
    #pragma unroll
    for (int i = 0; i < TM; i++)
        #pragma unroll
        for (int j = 0; j < TN; j++)
            acc[i][j] = 0.0f;

    for (int k0 = 0; k0 < K; k0 += BKT) {
        // ---- load A tile [BMT x BKT], store transposed As[k][m] ----
        #pragma unroll
        for (int l = 0; l < 2; l++) {
            int i   = tid + l * 256;          // 0..511 float4 index
            int row = i >> 2;                 // 0..127
            int kc  = (i & 3) * 4;            // 0,4,8,12
            float4 v = *(const float4*)(Ab + (size_t)row * K + (k0 + kc));
            As[kc + 0][row] = v.x;
            As[kc + 1][row] = v.y;
            As[kc + 2][row] = v.z;
            As[kc + 3][row] = v.w;
        }
        // ---- load B tile [BKT x BNT] ----
        #pragma unroll
        for (int l = 0; l < 2; l++) {
            int i   = tid + l * 256;
            int row = i >> 5;                 // 0..15
            int col = (i & 31) * 4;           // 0..124
            float4 v = *(const float4*)(Bb + (size_t)(k0 + row) * N + col);
            if (EPI == 0) {                   // fold (w / 17) into the load
                v.x *= bscale; v.y *= bscale; v.z *= bscale; v.w *= bscale;
            }
            *(float4*)&Bs[row][col] = v;
        }
        __syncthreads();

        #pragma unroll
        for (int k = 0; k < BKT; k++) {
            float regM[TM], regN[TN];
            *(float4*)&regM[0] = *(const float4*)&As[k][ty * TM];
            *(float4*)&regM[4] = *(const float4*)&As[k][ty * TM + 4];
            *(float4*)&regN[0] = *(const float4*)&Bs[k][tx * TN];
            *(float4*)&regN[4] = *(const float4*)&Bs[k][tx * TN + 4];
            #pragma unroll
            for (int i = 0; i < TM; i++)
                #pragma unroll
                for (int j = 0; j < TN; j++)
                    acc[i][j] += regM[i] * regN[j];
        }
        __syncthreads();
    }

    if (EPI == 1) {
        // Fused: out = (0.6<pre<=1 ? pre : 1) / prob[row]; mask = pre>0.6
        #pragma unroll
        for (int i = 0; i < TM; i++) {
            int r = bm + ty * TM + i;
            float rp = 1.0f / prob[r];
            #pragma unroll
            for (int jj = 0; jj < TN; jj += 4) {
                float4 ov, mv;
                float* po = (float*)&ov;
                float* pm = (float*)&mv;
                #pragma unroll
                for (int j = 0; j < 4; j++) {
                    float pre = acc[i][jj + j];
                    bool  gt  = pre > 0.6f;
                    float act = (gt && pre <= 1.0f) ? pre : 1.0f;
                    po[j] = act * rp;
                    pm[j] = gt ? 1.0f : 0.0f;
                }
                size_t off = (size_t)r * N + (bn + tx * TN + jj);
                *(float4*)(C  + off) = ov;
                *(float4*)(Mk + off) = mv;
            }
        }
    } else {
        #pragma unroll
        for (int i = 0; i < TM; i++) {
            int r = bm + ty * TM + i;
            #pragma unroll
            for (int jj = 0; jj < TN; jj += 4) {
                size_t off = (size_t)r * N + (bn + tx * TN + jj);
                *(float4*)(Cp + off) = *(const float4*)&acc[i][jj];
            }
        }
    }
}

extern "C" void kernel_launch(void* const* d_in, const int* in_sizes, int n_in,
                              void* d_out, int out_size)
{
    const float* inputs = (const float*)d_in[0];   // [1024, 8192]
    const float* adj    = (const float*)d_in[1];   // [8192, 1024]
    const float* prob   = (const float*)d_in[2];   // [8192]
    const float* w      = (const float*)d_in[3];   // [1024, 1024]

    float* out  = (float*)d_out;                              // [8192*8192]
    float* mask = (float*)d_out + (size_t)N_ROWS * D_COLS;    // [8192*8192]

    // GEMM1: T[8192,1024] = adj @ (w * (1/17))
    {
        dim3 grid(K_OUT / BNT, N_ROWS / BMT);   // (8, 64)
        sgemm_k<0><<<grid, 256>>>(adj, w, nullptr, nullptr, nullptr,
                                  N_ROWS, K_OUT, K_IN, 1.0f / 17.0f);
    }
    // GEMM2 + fused epilogue: pre = T @ inputs; out/mask
    {
        dim3 grid(D_COLS / BNT, N_ROWS / BMT);  // (64, 64)
        sgemm_k<1><<<grid, 256>>>(nullptr, inputs, out, mask, prob,
                                  N_ROWS, D_COLS, K_OUT, 1.0f);
    }
}

// round 4
// speedup vs baseline: 1.0000x; 1.0000x over previous
#include <cuda_runtime.h>
#include <cstdint>
#include <cstddef>

// Problem shapes (fixed by the dataset):
//   inputs : [OUT=1024, D=8192] f32   (d_in[0])
//   adj    : [N=8192, IN=1024] f32    (d_in[1])
//   prob_AU: [N=8192] f32             (d_in[2])
//   w      : [IN=1024, OUT=1024] f32  (d_in[3])
// out buffer: [N*D] activation-output followed by [N*D] mask (0/1 float).

#define BMT 128
#define BNT 128
#define BKT 16
#define TM 8
#define TN 8

static const int N_ROWS = 8192;   // N
static const int K_IN   = 1024;   // IN
static const int K_OUT  = 1024;   // OUT
static const int D_COLS = 8192;   // D

// Scratch for T = adj @ (w/17): 8192 x 1024 f32 = 32 MB
__device__ float g_T[(size_t)8192 * 1024];

// EPI == 0 : C = A @ (B*bscale)          (GEMM1, writes g_T)
// EPI == 1 : pre = g_T @ B, fused epilogue -> C (out) and Mk (mask)
template <int EPI>
__global__ __launch_bounds__(256, 2)
void sgemm_k(const float* __restrict__ A, const float* __restrict__ B,
             float* __restrict__ C, float* __restrict__ Mk,
             const float* __restrict__ prob,
             int M, int N, int K, float bscale)
{
    __shared__ float As[BKT][BMT + 4];   // +4 keeps 16B alignment, trims STS conflicts
    __shared__ float Bs[BKT][BNT];

    const int tid = threadIdx.x;
    const int tx  = tid & 15;            // 0..15 -> col group
    const int ty  = tid >> 4;            // 0..15 -> row group
    const int bm  = blockIdx.y * BMT;
    const int bn  = blockIdx.x * BNT;

    const float* Ap = (EPI == 1) ? (const float*)g_T : A;
    float*       Cp = (EPI == 1) ? C : (float*)g_T;

    const float* Ab = Ap + (size_t)bm * K;
    const float* Bb = B + bn;

    float acc[TM][TN];
    #pragma unroll
    for (int i = 0; i < TM; i++)
        #pragma unroll
        for (int j = 0; j < TN; j++)
            acc[i][j] = 0.0f;

    for (int k0 = 0; k0 < K; k0 += BKT) {
        // ---- load A tile [BMT x BKT], store transposed As[k][m] ----
        #pragma unroll
        for (int l = 0; l < 2; l++) {
            int i   = tid + l * 256;          // 0..511 float4 index
            int row = i >> 2;                 // 0..127
            int kc  = (i & 3) * 4;            // 0,4,8,12
            float4 v = *(const float4*)(Ab + (size_t)row * K + (k0 + kc));
            As[kc + 0][row] = v.x;
            As[kc + 1][row] = v.y;
            As[kc + 2][row] = v.z;
            As[kc + 3][row] = v.w;
        }
        // ---- load B tile [BKT x BNT] ----
        #pragma unroll
        for (int l = 0; l < 2; l++) {
            int i   = tid + l * 256;
            int row = i >> 5;                 // 0..15
            int col = (i & 31) * 4;           // 0..124
            float4 v = *(const float4*)(Bb + (size_t)(k0 + row) * N + col);
            if (EPI == 0) {                   // fold (w / 17) into the load
                v.x *= bscale; v.y *= bscale; v.z *= bscale; v.w *= bscale;
            }
            *(float4*)&Bs[row][col] = v;
        }
        __syncthreads();

        #pragma unroll
        for (int k = 0; k < BKT; k++) {
            float regM[TM], regN[TN];
            *(float4*)&regM[0] = *(const float4*)&As[k][ty * TM];
            *(float4*)&regM[4] = *(const float4*)&As[k][ty * TM + 4];
            *(float4*)&regN[0] = *(const float4*)&Bs[k][tx * TN];
            *(float4*)&regN[4] = *(const float4*)&Bs[k][tx * TN + 4];
            #pragma unroll
            for (int i = 0; i < TM; i++)
                #pragma unroll
                for (int j = 0; j < TN; j++)
                    acc[i][j] += regM[i] * regN[j];
        }
        __syncthreads();
    }

    if (EPI == 1) {
        // Fused: out = (0.6<pre<=1 ? pre : 1) / prob[row]; mask = pre>0.6
        #pragma unroll
        for (int i = 0; i < TM; i++) {
            int r = bm + ty * TM + i;
            float rp = 1.0f / prob[r];
            #pragma unroll
            for (int jj = 0; jj < TN; jj += 4) {
                float4 ov, mv;
                float* po = (float*)&ov;
                float* pm = (float*)&mv;
                #pragma unroll
                for (int j = 0; j < 4; j++) {
                    float pre = acc[i][jj + j];
                    bool  gt  = pre > 0.6f;
                    float act = (gt && pre <= 1.0f) ? pre : 1.0f;
                    po[j] = act * rp;
                    pm[j] = gt ? 1.0f : 0.0f;
                }
                size_t off = (size_t)r * N + (bn + tx * TN + jj);
                *(float4*)(C  + off) = ov;
                *(float4*)(Mk + off) = mv;
            }
        }
    } else {
        #pragma unroll
        for (int i = 0; i < TM; i++) {
            int r = bm + ty * TM + i;
            #pragma unroll
            for (int jj = 0; jj < TN; jj += 4) {
                size_t off = (size_t)r * N + (bn + tx * TN + jj);
                *(float4*)(Cp + off) = *(const float4*)&acc[i][jj];
            }
        }
    }
}

extern "C" void kernel_launch(void* const* d_in, const int* in_sizes, int n_in,
                              void* d_out, int out_size)
{
    const float* inputs = (const float*)d_in[0];   // [1024, 8192]
    const float* adj    = (const float*)d_in[1];   // [8192, 1024]
    const float* prob   = (const float*)d_in[2];   // [8192]
    const float* w      = (const float*)d_in[3];   // [1024, 1024]

    float* out  = (float*)d_out;                              // [8192*8192]
    float* mask = (float*)d_out + (size_t)N_ROWS * D_COLS;    // [8192*8192]

    // GEMM1: T[8192,1024] = adj @ (w * (1/17))
    {
        dim3 grid(K_OUT / BNT, N_ROWS / BMT);   // (8, 64)
        sgemm_k<0><<<grid, 256>>>(adj, w, nullptr, nullptr, nullptr,
                                  N_ROWS, K_OUT, K_IN, 1.0f / 17.0f);
    }
    // GEMM2 + fused epilogue: pre = T @ inputs; out/mask
    {
        dim3 grid(D_COLS / BNT, N_ROWS / BMT);  // (64, 64)
        sgemm_k<1><<<grid, 256>>>(nullptr, inputs, out, mask, prob,
                                  N_ROWS, D_COLS, K_OUT, 1.0f);
    }
}

// round 7
// speedup vs baseline: 1.0128x; 1.0128x over previous
#include <cuda_runtime.h>
#include <cstdint>
#include <cstddef>

// ============================================================================
// interAUGraphConv, GB300 (compute_103 PTX => no tcgen05; use mma.sync tf32)
//
//   GEMM1: T[8192,1024]   = adj @ (w/17)          -- fp32 SIMT, sequential-k
//   GEMM2: pre[8192,8192] = T @ inputs            -- 3xTF32 mma.sync
//   out = (0.6<pre<=1 ? pre : 1)/prob[row], mask = pre>0.6
//
// Elements with |pre-0.6| < DELTA are recomputed in sequential-k fp32
// (bitwise-identical order to the known-exact fp32 pipeline) by a fixup pass.
// ============================================================================

static const int KDIM = 1024;
static const int BM = 128, BN = 128, BK = 16;
static const int PAD = 20;
static const int TILE_WORDS = 128 * PAD;
static const int STAGE_B = 2 * TILE_WORDS * 4;     // 20480 bytes
static const int SMEM_TOTAL = 3 * STAGE_B;         // 61440

static const unsigned FIX_CAP = 1u << 22;          // 4M entries
#define DELTA 2.0e-3f

// ---- device scratch ----
__device__ float gBT2[(size_t)8192 * 1024];   // inputs^T [N=8192, K=1024]
__device__ float gT  [(size_t)8192 * 1024];   // T
__device__ unsigned gFixCnt;
__device__ unsigned gFix[FIX_CAP];

// ---------------------------------------------------------------------------
__device__ __forceinline__ uint32_t f2tf(float x) {
    uint32_t r;
    asm("cvt.rna.tf32.f32 %0, %1;" : "=r"(r) : "f"(x));
    return r;
}
__device__ __forceinline__ uint32_t smem_u32(const void* p) {
    uint32_t a;
    asm("{ .reg .u64 t; cvta.to.shared.u64 t, %1; cvt.u32.u64 %0, t; }" : "=r"(a) : "l"(p));
    return a;
}
#define CP_ASYNC16(saddr, gptr) \
    asm volatile("cp.async.cg.shared.global [%0], [%1], 16;" :: "r"(saddr), "l"(gptr))
#define CP_COMMIT() asm volatile("cp.async.commit_group;" ::: "memory")
#define CP_WAIT1()  asm volatile("cp.async.wait_group 1;" ::: "memory")

#define MMA_TF32(d, a, b)                                                   \
    asm volatile(                                                           \
        "mma.sync.aligned.m16n8k8.row.col.f32.tf32.tf32.f32 "               \
        "{%0,%1,%2,%3}, {%4,%5,%6,%7}, {%8,%9}, {%0,%1,%2,%3};"             \
        : "+f"((d)[0]), "+f"((d)[1]), "+f"((d)[2]), "+f"((d)[3])            \
        : "r"((a)[0]), "r"((a)[1]), "r"((a)[2]), "r"((a)[3]),               \
          "r"((b)[0]), "r"((b)[1]))

// ---------------------------------------------------------------------------
// transpose: inputs [1024, 8192] -> gBT2 [8192, 1024]
// ---------------------------------------------------------------------------
__global__ __launch_bounds__(256) void tkern(const float* __restrict__ in, int N) {
    __shared__ float t[32][33];
    int n0 = blockIdx.x * 32, k0 = blockIdx.y * 32;
    int tx = threadIdx.x, ty = threadIdx.y;    // (32, 8)
    #pragma unroll
    for (int p = 0; p < 4; p++)
        t[ty + p * 8][tx] = in[(size_t)(k0 + ty + p * 8) * N + n0 + tx];
    __syncthreads();
    #pragma unroll
    for (int p = 0; p < 4; p++)
        gBT2[(size_t)(n0 + ty + p * 8) * KDIM + k0 + tx] = t[tx][ty + p * 8];
}

__global__ void zkern() { gFixCnt = 0; }

// ---------------------------------------------------------------------------
// GEMM1: fp32 SIMT, sequential-k fma (matches the proven-exact pipeline).
// C = adj @ (w * 1/17) -> gT
// ---------------------------------------------------------------------------
__global__ __launch_bounds__(256, 2)
void sgemm1(const float* __restrict__ A, const float* __restrict__ B)
{
    __shared__ float As[BK][BM + 4];
    __shared__ float Bs[BK][BN];

    const int tid = threadIdx.x;
    const int tx  = tid & 15;
    const int ty  = tid >> 4;
    const int bm  = blockIdx.y * BM;
    const int bn  = blockIdx.x * BN;
    const int K = 1024, N = 1024;
    const float bscale = 1.0f / 17.0f;

    const float* Ab = A + (size_t)bm * K;
    const float* Bb = B + bn;

    float acc[8][8];
    #pragma unroll
    for (int i = 0; i < 8; i++)
        #pragma unroll
        for (int j = 0; j < 8; j++) acc[i][j] = 0.0f;

    for (int k0 = 0; k0 < K; k0 += BK) {
        #pragma unroll
        for (int l = 0; l < 2; l++) {
            int i = tid + l * 256, row = i >> 2, kc = (i & 3) * 4;
            float4 v = *(const float4*)(Ab + (size_t)row * K + (k0 + kc));
            As[kc + 0][row] = v.x; As[kc + 1][row] = v.y;
            As[kc + 2][row] = v.z; As[kc + 3][row] = v.w;
        }
        #pragma unroll
        for (int l = 0; l < 2; l++) {
            int i = tid + l * 256, row = i >> 5, col = (i & 31) * 4;
            float4 v = *(const float4*)(Bb + (size_t)(k0 + row) * N + col);
            v.x *= bscale; v.y *= bscale; v.z *= bscale; v.w *= bscale;
            *(float4*)&Bs[row][col] = v;
        }
        __syncthreads();
        #pragma unroll
        for (int k = 0; k < BK; k++) {
            float regM[8], regN[8];
            *(float4*)&regM[0] = *(const float4*)&As[k][ty * 8];
            *(float4*)&regM[4] = *(const float4*)&As[k][ty * 8 + 4];
            *(float4*)&regN[0] = *(const float4*)&Bs[k][tx * 8];
            *(float4*)&regN[4] = *(const float4*)&Bs[k][tx * 8 + 4];
            #pragma unroll
            for (int i = 0; i < 8; i++)
                #pragma unroll
                for (int j = 0; j < 8; j++)
                    acc[i][j] += regM[i] * regN[j];
        }
        __syncthreads();
    }
    #pragma unroll
    for (int i = 0; i < 8; i++) {
        int r = bm + ty * 8 + i;
        #pragma unroll
        for (int jj = 0; jj < 8; jj += 4)
            *(float4*)(gT + (size_t)r * N + (bn + tx * 8 + jj)) = *(const float4*)&acc[i][jj];
    }
}

// ---------------------------------------------------------------------------
// GEMM2: 3xTF32 mma.sync, fused activation epilogue + near-threshold flagging
// ---------------------------------------------------------------------------
__device__ __forceinline__ void fill_stage2(uint32_t sm, int buf, int kc,
                                            const float* __restrict__ A,
                                            const float* __restrict__ B,
                                            int bm, int bn, int tid) {
    uint32_t sA = sm + buf * STAGE_B;
    uint32_t sB = sA + TILE_WORDS * 4;
    #pragma unroll
    for (int t = 0; t < 2; t++) {
        int idx = tid + t * 256;
        int row = idx >> 2, q = idx & 3;
        uint32_t so = (uint32_t)(row * PAD + q * 4) * 4;
        CP_ASYNC16(sA + so, A + (size_t)(bm + row) * KDIM + kc * BK + q * 4);
        CP_ASYNC16(sB + so, B + (size_t)(bn + row) * KDIM + kc * BK + q * 4);
    }
}

__global__ __launch_bounds__(256, 1)
void gemm2(const float* __restrict__ A, const float* __restrict__ B,
           float* __restrict__ outp, float* __restrict__ maskp,
           const float* __restrict__ prob)
{
    extern __shared__ float smem[];
    uint32_t sm = smem_u32(smem);

    const int tid  = threadIdx.x;
    const int w    = tid >> 5;
    const int lane = tid & 31;
    const int g    = lane >> 2;
    const int tg   = lane & 3;
    const int warpM = (w & 1) * 64;
    const int warpN = (w >> 1) * 32;
    const int bm = blockIdx.y * BM;
    const int bn = blockIdx.x * BN;

    float d[4][4][4];
    #pragma unroll
    for (int i = 0; i < 4; i++)
        #pragma unroll
        for (int j = 0; j < 4; j++)
            #pragma unroll
            for (int c = 0; c < 4; c++) d[i][j][c] = 0.0f;

    fill_stage2(sm, 0, 0, A, B, bm, bn, tid); CP_COMMIT();
    fill_stage2(sm, 1, 1, A, B, bm, bn, tid); CP_COMMIT();

    const int NCH = KDIM / BK;   // 64
    for (int i = 0; i < NCH; i++) {
        CP_WAIT1();
        __syncthreads();
        int j = i + 2;
        if (j < NCH) fill_stage2(sm, j % 3, j, A, B, bm, bn, tid);
        CP_COMMIT();

        const float* As = smem + (i % 3) * (STAGE_B / 4);
        const float* Bs = As + TILE_WORDS;

        #pragma unroll
        for (int ks = 0; ks < 2; ks++) {
            float af[4][4], bf[4][2];
            #pragma unroll
            for (int mt = 0; mt < 4; mt++) {
                int m = warpM + mt * 16 + g;
                af[mt][0] = As[m * PAD + ks * 8 + tg];
                af[mt][1] = As[(m + 8) * PAD + ks * 8 + tg];
                af[mt][2] = As[m * PAD + ks * 8 + tg + 4];
                af[mt][3] = As[(m + 8) * PAD + ks * 8 + tg + 4];
            }
            #pragma unroll
            for (int nt = 0; nt < 4; nt++) {
                int n = warpN + nt * 8 + g;
                bf[nt][0] = Bs[n * PAD + ks * 8 + tg];
                bf[nt][1] = Bs[n * PAD + ks * 8 + tg + 4];
            }
            uint32_t ah[4][4], al[4][4], bh[4][2], bl[4][2];
            #pragma unroll
            for (int mt = 0; mt < 4; mt++)
                #pragma unroll
                for (int r = 0; r < 4; r++) {
                    float x = af[mt][r];
                    uint32_t h = f2tf(x);
                    ah[mt][r] = h;
                    al[mt][r] = f2tf(x - __uint_as_float(h));
                }
            #pragma unroll
            for (int nt = 0; nt < 4; nt++)
                #pragma unroll
                for (int r = 0; r < 2; r++) {
                    float x = bf[nt][r];
                    uint32_t h = f2tf(x);
                    bh[nt][r] = h;
                    bl[nt][r] = f2tf(x - __uint_as_float(h));
                }
            #pragma unroll
            for (int mt = 0; mt < 4; mt++)
                #pragma unroll
                for (int nt = 0; nt < 4; nt++) MMA_TF32(d[mt][nt], ah[mt], bh[nt]);
            #pragma unroll
            for (int mt = 0; mt < 4; mt++)
                #pragma unroll
                for (int nt = 0; nt < 4; nt++) MMA_TF32(d[mt][nt], al[mt], bh[nt]);
            #pragma unroll
            for (int mt = 0; mt < 4; mt++)
                #pragma unroll
                for (int nt = 0; nt < 4; nt++) MMA_TF32(d[mt][nt], ah[mt], bl[nt]);
        }
        __syncthreads();
    }

    // ---- epilogue: activation + mask + near-threshold flagging ----
    #pragma unroll
    for (int mt = 0; mt < 4; mt++) {
        int r0 = bm + warpM + mt * 16 + g;
        int r1 = r0 + 8;
        float rp0 = 1.0f / prob[r0];
        float rp1 = 1.0f / prob[r1];
        #pragma unroll
        for (int nt = 0; nt < 4; nt++) {
            int c = bn + warpN + nt * 8 + tg * 2;
            float2 o0, o1, m0, m1;
            #pragma unroll
            for (int q = 0; q < 4; q++) {
                float pre = d[mt][nt][q];
                int   rr  = (q < 2) ? r0 : r1;
                int   cc  = c + (q & 1);
                bool  gt  = pre > 0.6f;
                float act = (gt && pre <= 1.0f) ? pre : 1.0f;
                float rv  = act * ((q < 2) ? rp0 : rp1);
                float mv  = gt ? 1.0f : 0.0f;
                if (q == 0) { o0.x = rv; m0.x = mv; }
                else if (q == 1) { o0.y = rv; m0.y = mv; }
                else if (q == 2) { o1.x = rv; m1.x = mv; }
                else { o1.y = rv; m1.y = mv; }
                if (fabsf(pre - 0.6f) < DELTA) {
                    unsigned idx = atomicAdd(&gFixCnt, 1u);
                    if (idx < FIX_CAP)
                        gFix[idx] = ((unsigned)rr << 13) | (unsigned)cc;
                }
            }
            *(float2*)(outp  + (size_t)r0 * 8192 + c) = o0;
            *(float2*)(outp  + (size_t)r1 * 8192 + c) = o1;
            *(float2*)(maskp + (size_t)r0 * 8192 + c) = m0;
            *(float2*)(maskp + (size_t)r1 * 8192 + c) = m1;
        }
    }
}

// ---------------------------------------------------------------------------
// fixup: recompute flagged elements, sequential-k fp32 fma
// ---------------------------------------------------------------------------
__global__ __launch_bounds__(256)
void fixup(float* __restrict__ outp, float* __restrict__ maskp,
           const float* __restrict__ prob)
{
    unsigned cnt = gFixCnt;
    if (cnt > FIX_CAP) cnt = FIX_CAP;
    unsigned stride = gridDim.x * blockDim.x;
    for (unsigned i = blockIdx.x * blockDim.x + threadIdx.x; i < cnt; i += stride) {
        unsigned e = gFix[i];
        int m = e >> 13;
        int n = e & 8191;
        const float4* a = (const float4*)(gT + (size_t)m * KDIM);
        const float4* b = (const float4*)(gBT2 + (size_t)n * KDIM);
        float s = 0.0f;
        #pragma unroll 4
        for (int k = 0; k < KDIM / 4; k++) {
            float4 av = a[k], bv = b[k];
            s = fmaf(av.x, bv.x, s);
            s = fmaf(av.y, bv.y, s);
            s = fmaf(av.z, bv.z, s);
            s = fmaf(av.w, bv.w, s);
        }
        bool  gt  = s > 0.6f;
        float act = (gt && s <= 1.0f) ? s : 1.0f;
        size_t off = (size_t)m * 8192 + n;
        outp[off]  = act * (1.0f / prob[m]);
        maskp[off] = gt ? 1.0f : 0.0f;
    }
}

// ---------------------------------------------------------------------------
extern "C" void kernel_launch(void* const* d_in, const int* in_sizes, int n_in,
                              void* d_out, int out_size)
{
    const float* inputs = (const float*)d_in[0];   // [1024, 8192]
    const float* adj    = (const float*)d_in[1];   // [8192, 1024]
    const float* prob   = (const float*)d_in[2];   // [8192]
    const float* w      = (const float*)d_in[3];   // [1024, 1024]

    float* out  = (float*)d_out;
    float* mask = (float*)d_out + (size_t)8192 * 8192;

    cudaFuncSetAttribute(gemm2, cudaFuncAttributeMaxDynamicSharedMemorySize, SMEM_TOTAL);

    float* gBT2p; cudaGetSymbolAddress((void**)&gBT2p, gBT2);
    float* gTp;   cudaGetSymbolAddress((void**)&gTp,   gT);

    // inputs^T (K-major for mma row.col B operand)
    tkern<<<dim3(256, 32), dim3(32, 8)>>>(inputs, 8192);

    // GEMM1 (fp32 SIMT): T = adj @ (w/17)
    sgemm1<<<dim3(1024 / BN, 8192 / BM), 256>>>(adj, w);

    zkern<<<1, 1>>>();

    // GEMM2 (3xTF32): pre = T @ inputs, fused epilogue + flagging
    gemm2<<<dim3(8192 / BN, 8192 / BM), 256, SMEM_TOTAL>>>(gTp, gBT2p, out, mask, prob);

    // recompute near-threshold elements in exact-order fp32
    fixup<<<1024, 256>>>(out, mask, prob);
}